// round 15
// baseline (speedup 1.0000x reference)
#include <cuda_runtime.h>
#include <cuda_fp16.h>
#include <cstdint>

#define M_TOTAL 4608
#define D_MODEL 512
#define QKV_N   1536
#define N_HEADS 8
#define D_HEAD  64
#define KS      7
#define HW      48
#define IMG_PIX (HW * HW)
#define PLANE   (IMG_PIX * D_HEAD)

__device__ __half g_xh[M_TOTAL * D_MODEL];
__device__ __half g_wqkvh[D_MODEL * QKV_N];
__device__ __half g_wouth[D_MODEL * D_MODEL];
__device__ __half g_qkvh[M_TOTAL * QKV_N];
__device__ __half g_atth[M_TOTAL * D_MODEL];

#define K_OFF ((size_t)M_TOTAL * 512)
#define V_OFF ((size_t)M_TOTAL * 1024)

// ---------------------------------------------------------------------------
__device__ __forceinline__ void cp_async16(void* smem_dst, const void* gmem_src) {
    unsigned s = (unsigned)__cvta_generic_to_shared(smem_dst);
    asm volatile("cp.async.cg.shared.global [%0], [%1], 16;" :: "r"(s), "l"(gmem_src));
}
__device__ __forceinline__ void cp_commit() { asm volatile("cp.async.commit_group;"); }
template <int N>
__device__ __forceinline__ void cp_wait() { asm volatile("cp.async.wait_group %0;" :: "n"(N)); }

__device__ __forceinline__ void ldsm_x4(uint32_t r[4], const __half* p) {
    uint32_t a = (uint32_t)__cvta_generic_to_shared(p);
    asm volatile("ldmatrix.sync.aligned.m8n8.x4.shared.b16 {%0,%1,%2,%3}, [%4];"
                 : "=r"(r[0]), "=r"(r[1]), "=r"(r[2]), "=r"(r[3]) : "r"(a));
}
__device__ __forceinline__ void ldsm_x4t(uint32_t r[4], const __half* p) {
    uint32_t a = (uint32_t)__cvta_generic_to_shared(p);
    asm volatile("ldmatrix.sync.aligned.m8n8.x4.trans.shared.b16 {%0,%1,%2,%3}, [%4];"
                 : "=r"(r[0]), "=r"(r[1]), "=r"(r[2]), "=r"(r[3]) : "r"(a));
}
__device__ __forceinline__ void mma16816(float c[4], const uint32_t a[4],
                                         uint32_t b0, uint32_t b1) {
    asm volatile(
        "mma.sync.aligned.m16n8k16.row.col.f32.f16.f16.f32 "
        "{%0,%1,%2,%3}, {%4,%5,%6,%7}, {%8,%9}, {%0,%1,%2,%3};"
        : "+f"(c[0]), "+f"(c[1]), "+f"(c[2]), "+f"(c[3])
        : "r"(a[0]), "r"(a[1]), "r"(a[2]), "r"(a[3]), "r"(b0), "r"(b1));
}

// ---------------------------------------------------------------------------
__global__ void cvt3(const float* __restrict__ s0, __half* __restrict__ d0, int n0,
                     const float* __restrict__ s1, __half* __restrict__ d1, int n1,
                     const float* __restrict__ s2, __half* __restrict__ d2, int n2) {
    int i = blockIdx.x * blockDim.x + threadIdx.x;
    const int t0 = n0 >> 2, t1 = t0 + (n1 >> 2), t2 = t1 + (n2 >> 2);
    const float* s; __half* d; int j;
    if (i < t0)      { s = s0; d = d0; j = i; }
    else if (i < t1) { s = s1; d = d1; j = i - t0; }
    else if (i < t2) { s = s2; d = d2; j = i - t1; }
    else return;
    float4 v = ((const float4*)s)[j];
    ((__half2*)d)[j * 2]     = __floats2half2_rn(v.x, v.y);
    ((__half2*)d)[j * 2 + 1] = __floats2half2_rn(v.z, v.w);
}

// ---------------------------------------------------------------------------
// hgemm (QKV path, identical math to best run; + row_base for image split)
// ---------------------------------------------------------------------------
#define HA_STR 40
#define HB_STR 136
#define HSTAGE (128 * HA_STR + 32 * HB_STR)

template <bool SCATTER, int NSTG>
__global__ __launch_bounds__(256, 2) void hgemm(const __half* __restrict__ A,
                                                const __half* __restrict__ B,
                                                void* __restrict__ Cv,
                                                int M, int N, int K, int row_base) {
    extern __shared__ __half hsm[];

    const int t      = threadIdx.x;
    const int lane   = t & 31;
    const int wid    = t >> 5;
    const int warp_m = wid >> 1;
    const int warp_n = wid & 1;
    const int c_lane = lane & 3;
    const int r_lane = lane >> 2;

    const int row0 = row_base + blockIdx.y * 128;
    const int col0 = blockIdx.x * 128;
    const int NT = K / 32;

    auto load_tile = [&](int tile, int stage) {
        __half* As = hsm + stage * HSTAGE;
        __half* Bs = As + 128 * HA_STR;
        const __half* gA = A + (size_t)row0 * K + tile * 32;
        const __half* gB = B + (size_t)(tile * 32) * N + col0;
#pragma unroll
        for (int u = 0; u < 2; ++u) {
            int i = t + u * 256;
            int arow = i >> 2, acol = (i & 3) * 8;
            cp_async16(&As[arow * HA_STR + acol], gA + (size_t)arow * K + acol);
        }
#pragma unroll
        for (int u = 0; u < 2; ++u) {
            int i = t + u * 256;
            int brow = i >> 4, bcol = (i & 15) * 8;
            cp_async16(&Bs[brow * HB_STR + bcol], gB + (size_t)brow * N + bcol);
        }
        cp_commit();
    };

    float acc[2][8][4];
#pragma unroll
    for (int mt = 0; mt < 2; ++mt)
#pragma unroll
        for (int nt = 0; nt < 8; ++nt)
#pragma unroll
            for (int j = 0; j < 4; ++j) acc[mt][nt][j] = 0.f;

#pragma unroll
    for (int p = 0; p < NSTG - 1; ++p) {
        if (p < NT) load_tile(p, p);
        else cp_commit();
    }

    for (int tile = 0; tile < NT; ++tile) {
        cp_wait<NSTG - 2>();
        __syncthreads();

        const __half* As = hsm + (tile % NSTG) * HSTAGE;
        const __half* Bs = As + 128 * HA_STR;

#pragma unroll
        for (int ks = 0; ks < 2; ++ks) {
            const int k0 = ks * 16;
            uint32_t af[2][4];
            const __half* ap = As + (warp_m * 32 + (lane & 15)) * HA_STR
                                  + k0 + ((lane >> 4) << 3);
            ldsm_x4(af[0], ap);
            ldsm_x4(af[1], ap + 16 * HA_STR);
            uint32_t bf[4][4];
            const __half* bp = Bs + (k0 + ((lane >> 3) & 1) * 8 + (lane & 7)) * HB_STR
                                  + warp_n * 64 + (lane >> 4) * 8;
#pragma unroll
            for (int nb = 0; nb < 4; ++nb)
                ldsm_x4t(bf[nb], bp + nb * 16);
#pragma unroll
            for (int mt = 0; mt < 2; ++mt)
#pragma unroll
                for (int nt = 0; nt < 8; ++nt)
                    mma16816(acc[mt][nt], af[mt],
                             bf[nt >> 1][(nt & 1) * 2], bf[nt >> 1][(nt & 1) * 2 + 1]);
        }

        const int nxt = tile + NSTG - 1;
        if (nxt < NT) load_tile(nxt, nxt % NSTG);
        else cp_commit();
    }

    const int img_n = row0 >= IMG_PIX;
#pragma unroll
    for (int mt = 0; mt < 2; ++mt) {
        const int row_g = row0 + warp_m * 32 + mt * 16 + r_lane;
#pragma unroll
        for (int nt = 0; nt < 8; ++nt) {
            const int col_g = col0 + warp_n * 64 + nt * 8 + 2 * c_lane;
            if (!SCATTER) {
                float* C = (float*)Cv;
                *(float2*)&C[(size_t)row_g * N + col_g] =
                    make_float2(acc[mt][nt][0], acc[mt][nt][1]);
                *(float2*)&C[(size_t)(row_g + 8) * N + col_g] =
                    make_float2(acc[mt][nt][2], acc[mt][nt][3]);
            } else {
                __half* C = (__half*)Cv;
                const int which = col_g >> 9;
                const int g     = (col_g >> 6) & 7;
                const int e     = col_g & 63;
                const int p     = row_g - img_n * IMG_PIX;
                __half* dst = C + (size_t)which * K_OFF +
                              ((size_t)(img_n * 8 + g) * IMG_PIX + p) * 64 + e;
                *(__half2*)dst = __floats2half2_rn(acc[mt][nt][0], acc[mt][nt][1]);
                *(__half2*)(dst + 8 * 64) = __floats2half2_rn(acc[mt][nt][2], acc[mt][nt][3]);
            }
        }
    }
}

// ---------------------------------------------------------------------------
// hgemm_k64 (out projection, identical math to R13 best; + row_base)
// ---------------------------------------------------------------------------
#define KA_STR 72
#define KB_STR 136
#define KSTAGE (128 * KA_STR + 64 * KB_STR)

template <int NSTG>
__global__ __launch_bounds__(256, 1) void hgemm_k64(const __half* __restrict__ A,
                                                    const __half* __restrict__ B,
                                                    float* __restrict__ C,
                                                    int M, int N, int K, int row_base) {
    extern __shared__ __half hsm[];

    const int t      = threadIdx.x;
    const int lane   = t & 31;
    const int wid    = t >> 5;
    const int warp_m = wid >> 1;
    const int warp_n = wid & 1;
    const int c_lane = lane & 3;
    const int r_lane = lane >> 2;

    const int row0 = row_base + blockIdx.y * 128;
    const int col0 = blockIdx.x * 128;
    const int NT = K / 64;

    auto load_tile = [&](int tile, int stage) {
        __half* As = hsm + stage * KSTAGE;
        __half* Bs = As + 128 * KA_STR;
        const __half* gA = A + (size_t)row0 * K + tile * 64;
        const __half* gB = B + (size_t)(tile * 64) * N + col0;
#pragma unroll
        for (int u = 0; u < 4; ++u) {
            int i = t + u * 256;
            int arow = i >> 3, acol = (i & 7) * 8;
            cp_async16(&As[arow * KA_STR + acol], gA + (size_t)arow * K + acol);
        }
#pragma unroll
        for (int u = 0; u < 4; ++u) {
            int i = t + u * 256;
            int brow = i >> 4, bcol = (i & 15) * 8;
            cp_async16(&Bs[brow * KB_STR + bcol], gB + (size_t)brow * N + bcol);
        }
        cp_commit();
    };

    float acc[2][8][4];
#pragma unroll
    for (int mt = 0; mt < 2; ++mt)
#pragma unroll
        for (int nt = 0; nt < 8; ++nt)
#pragma unroll
            for (int j = 0; j < 4; ++j) acc[mt][nt][j] = 0.f;

#pragma unroll
    for (int p = 0; p < NSTG - 1; ++p) {
        if (p < NT) load_tile(p, p);
        else cp_commit();
    }

    uint32_t af[2][2][4];
    uint32_t bf[2][4][4];

    for (int tile = 0; tile < NT; ++tile) {
        cp_wait<NSTG - 2>();
        __syncthreads();

        const __half* As = hsm + (tile % NSTG) * KSTAGE;
        const __half* Bs = As + 128 * KA_STR;

        auto load_frags = [&](int ks, int buf) {
            const int k0 = ks * 16;
            const __half* ap = As + (warp_m * 32 + (lane & 15)) * KA_STR
                                  + k0 + ((lane >> 4) << 3);
            ldsm_x4(af[buf][0], ap);
            ldsm_x4(af[buf][1], ap + 16 * KA_STR);
            const __half* bp = Bs + (k0 + ((lane >> 3) & 1) * 8 + (lane & 7)) * KB_STR
                                  + warp_n * 64 + (lane >> 4) * 8;
#pragma unroll
            for (int nb = 0; nb < 4; ++nb)
                ldsm_x4t(bf[buf][nb], bp + nb * 16);
        };

        load_frags(0, 0);
#pragma unroll
        for (int ks = 0; ks < 4; ++ks) {
            const int cur = ks & 1;
            if (ks < 3) load_frags(ks + 1, cur ^ 1);
#pragma unroll
            for (int mt = 0; mt < 2; ++mt)
#pragma unroll
                for (int nt = 0; nt < 8; ++nt)
                    mma16816(acc[mt][nt], af[cur][mt],
                             bf[cur][nt >> 1][(nt & 1) * 2],
                             bf[cur][nt >> 1][(nt & 1) * 2 + 1]);
        }

        const int nxt = tile + NSTG - 1;
        if (nxt < NT) load_tile(nxt, nxt % NSTG);
        else cp_commit();
    }

#pragma unroll
    for (int mt = 0; mt < 2; ++mt) {
        const int row_g = row0 + warp_m * 32 + mt * 16 + r_lane;
#pragma unroll
        for (int nt = 0; nt < 8; ++nt) {
            const int col_g = col0 + warp_n * 64 + nt * 8 + 2 * c_lane;
            *(float2*)&C[(size_t)row_g * N + col_g] =
                make_float2(acc[mt][nt][0], acc[mt][nt][1]);
            *(float2*)&C[(size_t)(row_g + 8) * N + col_g] =
                make_float2(acc[mt][nt][2], acc[mt][nt][3]);
        }
    }
}

// ---------------------------------------------------------------------------
// natten5 (identical math to best run; + z_base for image split)
// ---------------------------------------------------------------------------
#define HN   224
#define HSTR 72
#define PSTR 232
#define NAT5_SMEM ((2 * HN * HSTR + 64 * HSTR + 64 * PSTR) * sizeof(__half) \
                   + 4 * 64 * sizeof(float))

__global__ __launch_bounds__(256) void natten5(const __half* __restrict__ qkv,
                                               __half* __restrict__ out, int z_base) {
    extern __shared__ __half shh[];
    __half* Kh = shh;
    __half* Vh = Kh + HN * HSTR;
    __half* Qs = Vh + HN * HSTR;
    __half* Ps = Qs + 64 * HSTR;
    float*  smax = (float*)(Ps + 64 * PSTR);
    float*  ssum = smax + 2 * 64;

    const int tid  = threadIdx.x;
    const int lane = tid & 31;
    const int wid  = tid >> 5;
    const int warp_m = wid >> 1;
    const int warp_n = wid & 1;

    const int tx0 = blockIdx.x * 8;
    const int ty0 = blockIdx.y * 8;
    const int z   = z_base + blockIdx.z;
    const int hy0 = min(max(ty0 - 3, 0), HW - 14);
    const int hx0 = min(max(tx0 - 3, 0), HW - 14);

    const __half* qp = qkv + (size_t)z * PLANE;
    const __half* kp = qkv + K_OFF + (size_t)z * PLANE;
    const __half* vp = qkv + V_OFF + (size_t)z * PLANE;

    for (int i = tid; i < 28 * 8; i += 256) {
        const int p = i >> 3;
        const int r = (p >> 1) * 16 + 14 + (p & 1);
        const int c = (i & 7) * 8;
        *(float4*)&Kh[r * HSTR + c] = make_float4(0.f, 0.f, 0.f, 0.f);
        *(float4*)&Vh[r * HSTR + c] = make_float4(0.f, 0.f, 0.f, 0.f);
    }
    for (int i = tid; i < 196 * 8; i += 256) {
        const int pl = i >> 3;
        const int hy = pl / 14, hx = pl - hy * 14;
        const int r  = hy * 16 + hx;
        const int c  = (i & 7) * 8;
        const size_t gp = (size_t)((hy0 + hy) * HW + hx0 + hx) * 64 + c;
        cp_async16(&Kh[r * HSTR + c], kp + gp);
        cp_async16(&Vh[r * HSTR + c], vp + gp);
    }
    for (int i = tid; i < 64 * 8; i += 256) {
        const int pl = i >> 3;
        const int py = pl >> 3, px = pl & 7;
        const int c  = (i & 7) * 8;
        const size_t gp = (size_t)((ty0 + py) * HW + tx0 + px) * 64 + c;
        cp_async16(&Qs[pl * HSTR + c], qp + gp);
    }
    cp_commit();
    cp_wait<0>();
    __syncthreads();

    float sacc[14][4];
#pragma unroll
    for (int j = 0; j < 14; ++j)
#pragma unroll
        for (int c = 0; c < 4; ++c) sacc[j][c] = 0.f;

#pragma unroll
    for (int ks = 0; ks < 4; ++ks) {
        const int k0 = ks * 16;
        uint32_t aq[4];
        ldsm_x4(aq, Qs + (warp_m * 16 + (lane & 15)) * HSTR + k0 + ((lane >> 4) << 3));
#pragma unroll
        for (int u = 0; u < 7; ++u) {
            const int n0 = warp_n * 112 + u * 16;
            uint32_t kf[4];
            ldsm_x4(kf, Kh + (n0 + (lane & 7) + ((lane >> 4) & 1) * 8) * HSTR
                        + k0 + ((lane >> 3) & 1) * 8);
            mma16816(sacc[2 * u],     aq, kf[0], kf[1]);
            mma16816(sacc[2 * u + 1], aq, kf[2], kf[3]);
        }
    }

    const int px   = lane >> 2;
    const int qa   = warp_m * 16 + px;
    const int qb   = qa + 8;
    const int ya   = ty0 + 2 * warp_m;
    const int yb   = ya + 1;
    const int syl_a = min(max(ya - 3, 0), HW - KS) - hy0;
    const int syl_b = min(max(yb - 3, 0), HW - KS) - hy0;
    const int sxl   = min(max(tx0 + px - 3, 0), HW - KS) - hx0;

    float ma = -1e30f, mb = -1e30f;
#pragma unroll
    for (int jt = 0; jt < 14; ++jt) {
        const int jg  = warp_n * 14 + jt;
        const int hy  = jg >> 1;
        const int hx0j = (jg & 1) * 8 + (lane & 3) * 2;
        const bool vya = (unsigned)(hy - syl_a) < 7u;
        const bool vyb = (unsigned)(hy - syl_b) < 7u;
        const bool vx0 = (unsigned)(hx0j - sxl) < 7u;
        const bool vx1 = (unsigned)(hx0j + 1 - sxl) < 7u;
        sacc[jt][0] = (vya && vx0) ? sacc[jt][0] * 0.125f : -1e30f;
        sacc[jt][1] = (vya && vx1) ? sacc[jt][1] * 0.125f : -1e30f;
        sacc[jt][2] = (vyb && vx0) ? sacc[jt][2] * 0.125f : -1e30f;
        sacc[jt][3] = (vyb && vx1) ? sacc[jt][3] * 0.125f : -1e30f;
        ma = fmaxf(ma, fmaxf(sacc[jt][0], sacc[jt][1]));
        mb = fmaxf(mb, fmaxf(sacc[jt][2], sacc[jt][3]));
    }
    ma = fmaxf(ma, __shfl_xor_sync(0xffffffffu, ma, 1));
    ma = fmaxf(ma, __shfl_xor_sync(0xffffffffu, ma, 2));
    mb = fmaxf(mb, __shfl_xor_sync(0xffffffffu, mb, 1));
    mb = fmaxf(mb, __shfl_xor_sync(0xffffffffu, mb, 2));
    if ((lane & 3) == 0) {
        smax[warp_n * 64 + qa] = ma;
        smax[warp_n * 64 + qb] = mb;
    }
    __syncthreads();
    const float Ma = fmaxf(smax[qa], smax[64 + qa]);
    const float Mb = fmaxf(smax[qb], smax[64 + qb]);

    float sa = 0.f, sb = 0.f;
#pragma unroll
    for (int jt = 0; jt < 14; ++jt) {
        const float p0 = __expf(sacc[jt][0] - Ma);
        const float p1 = __expf(sacc[jt][1] - Ma);
        const float p2 = __expf(sacc[jt][2] - Mb);
        const float p3 = __expf(sacc[jt][3] - Mb);
        sa += p0 + p1;
        sb += p2 + p3;
        const int col = warp_n * 112 + jt * 8 + (lane & 3) * 2;
        *(__half2*)&Ps[qa * PSTR + col] = __floats2half2_rn(p0, p1);
        *(__half2*)&Ps[qb * PSTR + col] = __floats2half2_rn(p2, p3);
    }
    sa += __shfl_xor_sync(0xffffffffu, sa, 1);
    sa += __shfl_xor_sync(0xffffffffu, sa, 2);
    sb += __shfl_xor_sync(0xffffffffu, sb, 1);
    sb += __shfl_xor_sync(0xffffffffu, sb, 2);
    if ((lane & 3) == 0) {
        ssum[warp_n * 64 + qa] = sa;
        ssum[warp_n * 64 + qb] = sb;
    }
    __syncthreads();

    float oacc[4][4];
#pragma unroll
    for (int nt = 0; nt < 4; ++nt)
#pragma unroll
        for (int c = 0; c < 4; ++c) oacc[nt][c] = 0.f;

#pragma unroll
    for (int t = 0; t < 14; ++t) {
        const int k0 = t * 16;
        uint32_t ap[4];
        ldsm_x4(ap, Ps + (warp_m * 16 + (lane & 15)) * PSTR + k0 + ((lane >> 4) << 3));
        const __half* vbase = Vh + (k0 + ((lane >> 3) & 1) * 8 + (lane & 7)) * HSTR
                                 + warp_n * 32 + ((lane >> 4) << 3);
#pragma unroll
        for (int nb = 0; nb < 2; ++nb) {
            uint32_t vf[4];
            ldsm_x4t(vf, vbase + nb * 16);
            mma16816(oacc[nb * 2],     ap, vf[0], vf[1]);
            mma16816(oacc[nb * 2 + 1], ap, vf[2], vf[3]);
        }
    }

    const float inva = 1.f / (ssum[qa] + ssum[64 + qa]);
    const float invb = 1.f / (ssum[qb] + ssum[64 + qb]);
    const int n = z >> 3;
    const int g = z & 7;
    const int gx = tx0 + px;
    const size_t rowa = ((size_t)n * IMG_PIX + ya * HW + gx) * D_MODEL + g * D_HEAD;
    const size_t rowb = ((size_t)n * IMG_PIX + yb * HW + gx) * D_MODEL + g * D_HEAD;
#pragma unroll
    for (int nt = 0; nt < 4; ++nt) {
        const int col = warp_n * 32 + nt * 8 + (lane & 3) * 2;
        *(__half2*)&out[rowa + col] =
            __floats2half2_rn(oacc[nt][0] * inva, oacc[nt][1] * inva);
        *(__half2*)&out[rowb + col] =
            __floats2half2_rn(oacc[nt][2] * invb, oacc[nt][3] * invb);
    }
}

// ---------------------------------------------------------------------------
extern "C" void kernel_launch(void* const* d_in, const int* in_sizes, int n_in,
                              void* d_out, int out_size) {
    const float* x     = (const float*)d_in[0];
    const float* w_qkv = (const float*)d_in[1];
    const float* w_out = (const float*)d_in[2];
    float* out = (float*)d_out;

    static __half *xh, *wqkvh, *wouth, *qkvh, *atth;
    static cudaStream_t s1;
    static cudaEvent_t eA, eDone;
    static int hsmem4 = 0, ksmem4 = 0;
    static bool init_done = false;
    if (!init_done) {
        cudaGetSymbolAddress((void**)&xh, g_xh);
        cudaGetSymbolAddress((void**)&wqkvh, g_wqkvh);
        cudaGetSymbolAddress((void**)&wouth, g_wouth);
        cudaGetSymbolAddress((void**)&qkvh, g_qkvh);
        cudaGetSymbolAddress((void**)&atth, g_atth);

        hsmem4 = 4 * HSTAGE * (int)sizeof(__half);
        ksmem4 = 4 * KSTAGE * (int)sizeof(__half);
        cudaFuncSetAttribute((const void*)hgemm<true, 4>,
                             cudaFuncAttributeMaxDynamicSharedMemorySize, hsmem4);
        cudaFuncSetAttribute((const void*)hgemm_k64<4>,
                             cudaFuncAttributeMaxDynamicSharedMemorySize, ksmem4);
        cudaFuncSetAttribute((const void*)natten5,
                             cudaFuncAttributeMaxDynamicSharedMemorySize, (int)NAT5_SMEM);

        cudaStreamCreateWithFlags(&s1, cudaStreamNonBlocking);
        cudaEventCreateWithFlags(&eA, cudaEventDisableTiming);
        cudaEventCreateWithFlags(&eDone, cudaEventDisableTiming);
        init_done = true;
    }

    const int HALF_Y = (IMG_PIX / 128);   // 18 row-blocks per image

    // s0 (capture stream = default stream 0 used by harness? use legacy 0):
    // The harness invokes kernel_launch on its capture stream; default-stream
    // launches below are captured. For the fork we use explicit events.
    cudaStream_t s0 = 0;

    // 0) Convert inputs to fp16
    const int NX = M_TOTAL * D_MODEL, NWQ = D_MODEL * QKV_N, NWO = D_MODEL * D_MODEL;
    const int tot4 = (NX + NWQ + NWO) / 4;
    cvt3<<<(tot4 + 255) / 256, 256, 0, s0>>>(x, xh, NX, w_qkv, wqkvh, NWQ, w_out, wouth, NWO);

    // 1a) QKV image 0
    hgemm<true, 4><<<dim3(QKV_N / 128, HALF_Y), 256, hsmem4, s0>>>(
        xh, wqkvh, qkvh, M_TOTAL, QKV_N, D_MODEL, 0);
    cudaEventRecord(eA, s0);

    // 1b) QKV image 1 (s0)  ∥  2a) natten image 0 (s1)
    hgemm<true, 4><<<dim3(QKV_N / 128, HALF_Y), 256, hsmem4, s0>>>(
        xh, wqkvh, qkvh, M_TOTAL, QKV_N, D_MODEL, IMG_PIX);
    cudaStreamWaitEvent(s1, eA, 0);
    natten5<<<dim3(HW / 8, HW / 8, N_HEADS), 256, NAT5_SMEM, s1>>>(qkvh, atth, 0);

    // 2b) natten image 1 (s0)  ∥  3a) out image 0 (s1)
    natten5<<<dim3(HW / 8, HW / 8, N_HEADS), 256, NAT5_SMEM, s0>>>(qkvh, atth, N_HEADS);
    hgemm_k64<4><<<dim3(D_MODEL / 128, HALF_Y), 256, ksmem4, s1>>>(
        atth, wouth, out, M_TOTAL, D_MODEL, D_MODEL, 0);
    cudaEventRecord(eDone, s1);

    // 3b) out image 1 (s0, after joining s1)
    cudaStreamWaitEvent(s0, eDone, 0);
    hgemm_k64<4><<<dim3(D_MODEL / 128, HALF_Y), 256, ksmem4, s0>>>(
        atth, wouth, out, M_TOTAL, D_MODEL, D_MODEL, IMG_PIX);
}

// round 16
// speedup vs baseline: 1.2125x; 1.2125x over previous
#include <cuda_runtime.h>
#include <cuda_fp16.h>
#include <cstdint>

#define M_TOTAL 4608
#define D_MODEL 512
#define QKV_N   1536
#define N_HEADS 8
#define D_HEAD  64
#define KS      7
#define HW      48
#define IMG_PIX (HW * HW)
#define PLANE   (IMG_PIX * D_HEAD)

__device__ __half g_wqkvh[D_MODEL * QKV_N];
__device__ __half g_wouth[D_MODEL * D_MODEL];
__device__ __half g_qkvh[M_TOTAL * QKV_N];
__device__ __half g_atth[M_TOTAL * D_MODEL];

#define K_OFF ((size_t)M_TOTAL * 512)
#define V_OFF ((size_t)M_TOTAL * 1024)

// ---------------------------------------------------------------------------
__device__ __forceinline__ void cp_async16(void* smem_dst, const void* gmem_src) {
    unsigned s = (unsigned)__cvta_generic_to_shared(smem_dst);
    asm volatile("cp.async.cg.shared.global [%0], [%1], 16;" :: "r"(s), "l"(gmem_src));
}
__device__ __forceinline__ void cp_commit() { asm volatile("cp.async.commit_group;"); }
template <int N>
__device__ __forceinline__ void cp_wait() { asm volatile("cp.async.wait_group %0;" :: "n"(N)); }

__device__ __forceinline__ void ldsm_x4(uint32_t r[4], const __half* p) {
    uint32_t a = (uint32_t)__cvta_generic_to_shared(p);
    asm volatile("ldmatrix.sync.aligned.m8n8.x4.shared.b16 {%0,%1,%2,%3}, [%4];"
                 : "=r"(r[0]), "=r"(r[1]), "=r"(r[2]), "=r"(r[3]) : "r"(a));
}
__device__ __forceinline__ void ldsm_x4t(uint32_t r[4], const __half* p) {
    uint32_t a = (uint32_t)__cvta_generic_to_shared(p);
    asm volatile("ldmatrix.sync.aligned.m8n8.x4.trans.shared.b16 {%0,%1,%2,%3}, [%4];"
                 : "=r"(r[0]), "=r"(r[1]), "=r"(r[2]), "=r"(r[3]) : "r"(a));
}
__device__ __forceinline__ void mma16816(float c[4], const uint32_t a[4],
                                         uint32_t b0, uint32_t b1) {
    asm volatile(
        "mma.sync.aligned.m16n8k16.row.col.f32.f16.f16.f32 "
        "{%0,%1,%2,%3}, {%4,%5,%6,%7}, {%8,%9}, {%0,%1,%2,%3};"
        : "+f"(c[0]), "+f"(c[1]), "+f"(c[2]), "+f"(c[3])
        : "r"(a[0]), "r"(a[1]), "r"(a[2]), "r"(a[3]), "r"(b0), "r"(b1));
}

// ---------------------------------------------------------------------------
// cvt2: f32 -> f16 for the two weight matrices only.
// ---------------------------------------------------------------------------
__global__ void cvt2(const float* __restrict__ s0, __half* __restrict__ d0, int n0,
                     const float* __restrict__ s1, __half* __restrict__ d1, int n1) {
    int i = blockIdx.x * blockDim.x + threadIdx.x;
    const int t0 = n0 >> 2, t1 = t0 + (n1 >> 2);
    const float* s; __half* d; int j;
    if (i < t0)      { s = s0; d = d0; j = i; }
    else if (i < t1) { s = s1; d = d1; j = i - t0; }
    else return;
    float4 v = ((const float4*)s)[j];
    ((__half2*)d)[j * 2]     = __floats2half2_rn(v.x, v.y);
    ((__half2*)d)[j * 2 + 1] = __floats2half2_rn(v.z, v.w);
}

#define HA_STR 40
#define HB_STR 136
#define ASZ (128 * HA_STR)          // A stage, halves
#define BSZ (32 * HB_STR)           // B stage, halves
#define NSTG 4

// ---------------------------------------------------------------------------
// hgemm_qkv: QKV projection, A read as f32 (fused conversion), B fp16 via
// 4-stage cp.async ring. A double-buffered in smem via LDG f32 -> cvt -> STS.
// 256 threads, 8 warps (4m x 2n), warp tile 32x64, plane-scatter epilogue.
// ---------------------------------------------------------------------------
__global__ __launch_bounds__(256, 2) void hgemm_qkv(const float* __restrict__ A,
                                                    const __half* __restrict__ B,
                                                    __half* __restrict__ C,
                                                    int M, int N, int K) {
    extern __shared__ __half hsm[];
    __half* As2 = hsm;                  // [2][128][HA_STR]
    __half* Bsr = hsm + 2 * ASZ;        // [NSTG][32][HB_STR]

    const int t      = threadIdx.x;
    const int lane   = t & 31;
    const int wid    = t >> 5;
    const int warp_m = wid >> 1;
    const int warp_n = wid & 1;
    const int c_lane = lane & 3;
    const int r_lane = lane >> 2;

    const int row0 = blockIdx.y * 128;
    const int col0 = blockIdx.x * 128;
    const int NT = K / 32;

    // A chunk mapping: i = t + u*256, arow = i>>3, acol = (i&7)*4 (f32 cols)
    auto load_A_regs = [&](int tile, float4 v[4]) {
        const float* gA = A + (size_t)row0 * K + tile * 32;
#pragma unroll
        for (int u = 0; u < 4; ++u) {
            const int i = t + u * 256;
            const int arow = i >> 3, acol = (i & 7) * 4;
            v[u] = *(const float4*)(gA + (size_t)arow * K + acol);
        }
    };
    auto sts_A = [&](const float4 v[4], int buf) {
        __half* As = As2 + buf * ASZ;
#pragma unroll
        for (int u = 0; u < 4; ++u) {
            const int i = t + u * 256;
            const int arow = i >> 3, acol = (i & 7) * 4;
            __half2 h0 = __floats2half2_rn(v[u].x, v[u].y);
            __half2 h1 = __floats2half2_rn(v[u].z, v[u].w);
            uint2 pk;
            pk.x = *(uint32_t*)&h0;
            pk.y = *(uint32_t*)&h1;
            *(uint2*)&As[arow * HA_STR + acol] = pk;
        }
    };
    auto load_B = [&](int tile, int stage) {
        __half* Bs = Bsr + stage * BSZ;
        const __half* gB = B + (size_t)(tile * 32) * N + col0;
#pragma unroll
        for (int u = 0; u < 2; ++u) {
            const int i = t + u * 256;
            const int brow = i >> 4, bcol = (i & 15) * 8;
            cp_async16(&Bs[brow * HB_STR + bcol], gB + (size_t)brow * N + bcol);
        }
        cp_commit();
    };

    float acc[2][8][4];
#pragma unroll
    for (int mt = 0; mt < 2; ++mt)
#pragma unroll
        for (int nt = 0; nt < 8; ++nt)
#pragma unroll
            for (int j = 0; j < 4; ++j) acc[mt][nt][j] = 0.f;

    float4 av[4];
    load_A_regs(0, av);
#pragma unroll
    for (int p = 0; p < NSTG - 1; ++p) {
        if (p < NT) load_B(p, p);
        else cp_commit();
    }
    sts_A(av, 0);

    for (int tile = 0; tile < NT; ++tile) {
        cp_wait<NSTG - 2>();
        __syncthreads();   // Bs[tile%NSTG] ready; As[tile&1] writes visible

        if (tile + 1 < NT) load_A_regs(tile + 1, av);

        const __half* As = As2 + (tile & 1) * ASZ;
        const __half* Bs = Bsr + (tile % NSTG) * BSZ;

#pragma unroll
        for (int ks = 0; ks < 2; ++ks) {
            const int k0 = ks * 16;
            uint32_t af[2][4];
            const __half* ap = As + (warp_m * 32 + (lane & 15)) * HA_STR
                                  + k0 + ((lane >> 4) << 3);
            ldsm_x4(af[0], ap);
            ldsm_x4(af[1], ap + 16 * HA_STR);
            uint32_t bf[4][4];
            const __half* bp = Bs + (k0 + ((lane >> 3) & 1) * 8 + (lane & 7)) * HB_STR
                                  + warp_n * 64 + (lane >> 4) * 8;
#pragma unroll
            for (int nb = 0; nb < 4; ++nb)
                ldsm_x4t(bf[nb], bp + nb * 16);
#pragma unroll
            for (int mt = 0; mt < 2; ++mt)
#pragma unroll
                for (int nt = 0; nt < 8; ++nt)
                    mma16816(acc[mt][nt], af[mt],
                             bf[nt >> 1][(nt & 1) * 2], bf[nt >> 1][(nt & 1) * 2 + 1]);
        }

        const int nxt = tile + NSTG - 1;
        if (nxt < NT) load_B(nxt, nxt % NSTG);
        else cp_commit();
        if (tile + 1 < NT) sts_A(av, (tile + 1) & 1);
    }

    // Plane-scatter epilogue (fp16 q/k/v planes)
    const int img_n = row0 >= IMG_PIX;
#pragma unroll
    for (int mt = 0; mt < 2; ++mt) {
        const int row_g = row0 + warp_m * 32 + mt * 16 + r_lane;
#pragma unroll
        for (int nt = 0; nt < 8; ++nt) {
            const int col_g = col0 + warp_n * 64 + nt * 8 + 2 * c_lane;
            const int which = col_g >> 9;
            const int g     = (col_g >> 6) & 7;
            const int e     = col_g & 63;
            const int p     = row_g - img_n * IMG_PIX;
            __half* dst = C + (size_t)which * K_OFF +
                          ((size_t)(img_n * 8 + g) * IMG_PIX + p) * 64 + e;
            *(__half2*)dst = __floats2half2_rn(acc[mt][nt][0], acc[mt][nt][1]);
            *(__half2*)(dst + 8 * 64) = __floats2half2_rn(acc[mt][nt][2], acc[mt][nt][3]);
        }
    }
}

// ---------------------------------------------------------------------------
// hgemm_k64 (out projection) — identical to R13 best.
// ---------------------------------------------------------------------------
#define KA_STR 72
#define KB_STR 136
#define KSTAGE (128 * KA_STR + 64 * KB_STR)

template <int NS>
__global__ __launch_bounds__(256, 1) void hgemm_k64(const __half* __restrict__ A,
                                                    const __half* __restrict__ B,
                                                    float* __restrict__ C,
                                                    int M, int N, int K) {
    extern __shared__ __half hsm[];

    const int t      = threadIdx.x;
    const int lane   = t & 31;
    const int wid    = t >> 5;
    const int warp_m = wid >> 1;
    const int warp_n = wid & 1;
    const int c_lane = lane & 3;
    const int r_lane = lane >> 2;

    const int row0 = blockIdx.y * 128;
    const int col0 = blockIdx.x * 128;
    const int NT = K / 64;

    auto load_tile = [&](int tile, int stage) {
        __half* As = hsm + stage * KSTAGE;
        __half* Bs = As + 128 * KA_STR;
        const __half* gA = A + (size_t)row0 * K + tile * 64;
        const __half* gB = B + (size_t)(tile * 64) * N + col0;
#pragma unroll
        for (int u = 0; u < 4; ++u) {
            int i = t + u * 256;
            int arow = i >> 3, acol = (i & 7) * 8;
            cp_async16(&As[arow * KA_STR + acol], gA + (size_t)arow * K + acol);
        }
#pragma unroll
        for (int u = 0; u < 4; ++u) {
            int i = t + u * 256;
            int brow = i >> 4, bcol = (i & 15) * 8;
            cp_async16(&Bs[brow * KB_STR + bcol], gB + (size_t)brow * N + bcol);
        }
        cp_commit();
    };

    float acc[2][8][4];
#pragma unroll
    for (int mt = 0; mt < 2; ++mt)
#pragma unroll
        for (int nt = 0; nt < 8; ++nt)
#pragma unroll
            for (int j = 0; j < 4; ++j) acc[mt][nt][j] = 0.f;

#pragma unroll
    for (int p = 0; p < NS - 1; ++p) {
        if (p < NT) load_tile(p, p);
        else cp_commit();
    }

    uint32_t af[2][2][4];
    uint32_t bf[2][4][4];

    for (int tile = 0; tile < NT; ++tile) {
        cp_wait<NS - 2>();
        __syncthreads();

        const __half* As = hsm + (tile % NS) * KSTAGE;
        const __half* Bs = As + 128 * KA_STR;

        auto load_frags = [&](int ks, int buf) {
            const int k0 = ks * 16;
            const __half* ap = As + (warp_m * 32 + (lane & 15)) * KA_STR
                                  + k0 + ((lane >> 4) << 3);
            ldsm_x4(af[buf][0], ap);
            ldsm_x4(af[buf][1], ap + 16 * KA_STR);
            const __half* bp = Bs + (k0 + ((lane >> 3) & 1) * 8 + (lane & 7)) * KB_STR
                                  + warp_n * 64 + (lane >> 4) * 8;
#pragma unroll
            for (int nb = 0; nb < 4; ++nb)
                ldsm_x4t(bf[buf][nb], bp + nb * 16);
        };

        load_frags(0, 0);
#pragma unroll
        for (int ks = 0; ks < 4; ++ks) {
            const int cur = ks & 1;
            if (ks < 3) load_frags(ks + 1, cur ^ 1);
#pragma unroll
            for (int mt = 0; mt < 2; ++mt)
#pragma unroll
                for (int nt = 0; nt < 8; ++nt)
                    mma16816(acc[mt][nt], af[cur][mt],
                             bf[cur][nt >> 1][(nt & 1) * 2],
                             bf[cur][nt >> 1][(nt & 1) * 2 + 1]);
        }

        const int nxt = tile + NS - 1;
        if (nxt < NT) load_tile(nxt, nxt % NS);
        else cp_commit();
    }

#pragma unroll
    for (int mt = 0; mt < 2; ++mt) {
        const int row_g = row0 + warp_m * 32 + mt * 16 + r_lane;
#pragma unroll
        for (int nt = 0; nt < 8; ++nt) {
            const int col_g = col0 + warp_n * 64 + nt * 8 + 2 * c_lane;
            *(float2*)&C[(size_t)row_g * N + col_g] =
                make_float2(acc[mt][nt][0], acc[mt][nt][1]);
            *(float2*)&C[(size_t)(row_g + 8) * N + col_g] =
                make_float2(acc[mt][nt][2], acc[mt][nt][3]);
        }
    }
}

// ---------------------------------------------------------------------------
// natten5 — identical to R13 best.
// ---------------------------------------------------------------------------
#define HN   224
#define HSTR 72
#define PSTR 232
#define NAT5_SMEM ((2 * HN * HSTR + 64 * HSTR + 64 * PSTR) * sizeof(__half) \
                   + 4 * 64 * sizeof(float))

__global__ __launch_bounds__(256) void natten5(const __half* __restrict__ qkv,
                                               __half* __restrict__ out) {
    extern __shared__ __half shh[];
    __half* Kh = shh;
    __half* Vh = Kh + HN * HSTR;
    __half* Qs = Vh + HN * HSTR;
    __half* Ps = Qs + 64 * HSTR;
    float*  smax = (float*)(Ps + 64 * PSTR);
    float*  ssum = smax + 2 * 64;

    const int tid  = threadIdx.x;
    const int lane = tid & 31;
    const int wid  = tid >> 5;
    const int warp_m = wid >> 1;
    const int warp_n = wid & 1;

    const int tx0 = blockIdx.x * 8;
    const int ty0 = blockIdx.y * 8;
    const int z   = blockIdx.z;
    const int hy0 = min(max(ty0 - 3, 0), HW - 14);
    const int hx0 = min(max(tx0 - 3, 0), HW - 14);

    const __half* qp = qkv + (size_t)z * PLANE;
    const __half* kp = qkv + K_OFF + (size_t)z * PLANE;
    const __half* vp = qkv + V_OFF + (size_t)z * PLANE;

    for (int i = tid; i < 28 * 8; i += 256) {
        const int p = i >> 3;
        const int r = (p >> 1) * 16 + 14 + (p & 1);
        const int c = (i & 7) * 8;
        *(float4*)&Kh[r * HSTR + c] = make_float4(0.f, 0.f, 0.f, 0.f);
        *(float4*)&Vh[r * HSTR + c] = make_float4(0.f, 0.f, 0.f, 0.f);
    }
    for (int i = tid; i < 196 * 8; i += 256) {
        const int pl = i >> 3;
        const int hy = pl / 14, hx = pl - hy * 14;
        const int r  = hy * 16 + hx;
        const int c  = (i & 7) * 8;
        const size_t gp = (size_t)((hy0 + hy) * HW + hx0 + hx) * 64 + c;
        cp_async16(&Kh[r * HSTR + c], kp + gp);
        cp_async16(&Vh[r * HSTR + c], vp + gp);
    }
    for (int i = tid; i < 64 * 8; i += 256) {
        const int pl = i >> 3;
        const int py = pl >> 3, px = pl & 7;
        const int c  = (i & 7) * 8;
        const size_t gp = (size_t)((ty0 + py) * HW + tx0 + px) * 64 + c;
        cp_async16(&Qs[pl * HSTR + c], qp + gp);
    }
    cp_commit();
    cp_wait<0>();
    __syncthreads();

    float sacc[14][4];
#pragma unroll
    for (int j = 0; j < 14; ++j)
#pragma unroll
        for (int c = 0; c < 4; ++c) sacc[j][c] = 0.f;

#pragma unroll
    for (int ks = 0; ks < 4; ++ks) {
        const int k0 = ks * 16;
        uint32_t aq[4];
        ldsm_x4(aq, Qs + (warp_m * 16 + (lane & 15)) * HSTR + k0 + ((lane >> 4) << 3));
#pragma unroll
        for (int u = 0; u < 7; ++u) {
            const int n0 = warp_n * 112 + u * 16;
            uint32_t kf[4];
            ldsm_x4(kf, Kh + (n0 + (lane & 7) + ((lane >> 4) & 1) * 8) * HSTR
                        + k0 + ((lane >> 3) & 1) * 8);
            mma16816(sacc[2 * u],     aq, kf[0], kf[1]);
            mma16816(sacc[2 * u + 1], aq, kf[2], kf[3]);
        }
    }

    const int px   = lane >> 2;
    const int qa   = warp_m * 16 + px;
    const int qb   = qa + 8;
    const int ya   = ty0 + 2 * warp_m;
    const int yb   = ya + 1;
    const int syl_a = min(max(ya - 3, 0), HW - KS) - hy0;
    const int syl_b = min(max(yb - 3, 0), HW - KS) - hy0;
    const int sxl   = min(max(tx0 + px - 3, 0), HW - KS) - hx0;

    float ma = -1e30f, mb = -1e30f;
#pragma unroll
    for (int jt = 0; jt < 14; ++jt) {
        const int jg  = warp_n * 14 + jt;
        const int hy  = jg >> 1;
        const int hx0j = (jg & 1) * 8 + (lane & 3) * 2;
        const bool vya = (unsigned)(hy - syl_a) < 7u;
        const bool vyb = (unsigned)(hy - syl_b) < 7u;
        const bool vx0 = (unsigned)(hx0j - sxl) < 7u;
        const bool vx1 = (unsigned)(hx0j + 1 - sxl) < 7u;
        sacc[jt][0] = (vya && vx0) ? sacc[jt][0] * 0.125f : -1e30f;
        sacc[jt][1] = (vya && vx1) ? sacc[jt][1] * 0.125f : -1e30f;
        sacc[jt][2] = (vyb && vx0) ? sacc[jt][2] * 0.125f : -1e30f;
        sacc[jt][3] = (vyb && vx1) ? sacc[jt][3] * 0.125f : -1e30f;
        ma = fmaxf(ma, fmaxf(sacc[jt][0], sacc[jt][1]));
        mb = fmaxf(mb, fmaxf(sacc[jt][2], sacc[jt][3]));
    }
    ma = fmaxf(ma, __shfl_xor_sync(0xffffffffu, ma, 1));
    ma = fmaxf(ma, __shfl_xor_sync(0xffffffffu, ma, 2));
    mb = fmaxf(mb, __shfl_xor_sync(0xffffffffu, mb, 1));
    mb = fmaxf(mb, __shfl_xor_sync(0xffffffffu, mb, 2));
    if ((lane & 3) == 0) {
        smax[warp_n * 64 + qa] = ma;
        smax[warp_n * 64 + qb] = mb;
    }
    __syncthreads();
    const float Ma = fmaxf(smax[qa], smax[64 + qa]);
    const float Mb = fmaxf(smax[qb], smax[64 + qb]);

    float sa = 0.f, sb = 0.f;
#pragma unroll
    for (int jt = 0; jt < 14; ++jt) {
        const float p0 = __expf(sacc[jt][0] - Ma);
        const float p1 = __expf(sacc[jt][1] - Ma);
        const float p2 = __expf(sacc[jt][2] - Mb);
        const float p3 = __expf(sacc[jt][3] - Mb);
        sa += p0 + p1;
        sb += p2 + p3;
        const int col = warp_n * 112 + jt * 8 + (lane & 3) * 2;
        *(__half2*)&Ps[qa * PSTR + col] = __floats2half2_rn(p0, p1);
        *(__half2*)&Ps[qb * PSTR + col] = __floats2half2_rn(p2, p3);
    }
    sa += __shfl_xor_sync(0xffffffffu, sa, 1);
    sa += __shfl_xor_sync(0xffffffffu, sa, 2);
    sb += __shfl_xor_sync(0xffffffffu, sb, 1);
    sb += __shfl_xor_sync(0xffffffffu, sb, 2);
    if ((lane & 3) == 0) {
        ssum[warp_n * 64 + qa] = sa;
        ssum[warp_n * 64 + qb] = sb;
    }
    __syncthreads();

    float oacc[4][4];
#pragma unroll
    for (int nt = 0; nt < 4; ++nt)
#pragma unroll
        for (int c = 0; c < 4; ++c) oacc[nt][c] = 0.f;

#pragma unroll
    for (int t = 0; t < 14; ++t) {
        const int k0 = t * 16;
        uint32_t ap[4];
        ldsm_x4(ap, Ps + (warp_m * 16 + (lane & 15)) * PSTR + k0 + ((lane >> 4) << 3));
        const __half* vbase = Vh + (k0 + ((lane >> 3) & 1) * 8 + (lane & 7)) * HSTR
                                 + warp_n * 32 + ((lane >> 4) << 3);
#pragma unroll
        for (int nb = 0; nb < 2; ++nb) {
            uint32_t vf[4];
            ldsm_x4t(vf, vbase + nb * 16);
            mma16816(oacc[nb * 2],     ap, vf[0], vf[1]);
            mma16816(oacc[nb * 2 + 1], ap, vf[2], vf[3]);
        }
    }

    const float inva = 1.f / (ssum[qa] + ssum[64 + qa]);
    const float invb = 1.f / (ssum[qb] + ssum[64 + qb]);
    const int n = z >> 3;
    const int g = z & 7;
    const int gx = tx0 + px;
    const size_t rowa = ((size_t)n * IMG_PIX + ya * HW + gx) * D_MODEL + g * D_HEAD;
    const size_t rowb = ((size_t)n * IMG_PIX + yb * HW + gx) * D_MODEL + g * D_HEAD;
#pragma unroll
    for (int nt = 0; nt < 4; ++nt) {
        const int col = warp_n * 32 + nt * 8 + (lane & 3) * 2;
        *(__half2*)&out[rowa + col] =
            __floats2half2_rn(oacc[nt][0] * inva, oacc[nt][1] * inva);
        *(__half2*)&out[rowb + col] =
            __floats2half2_rn(oacc[nt][2] * invb, oacc[nt][3] * invb);
    }
}

// ---------------------------------------------------------------------------
extern "C" void kernel_launch(void* const* d_in, const int* in_sizes, int n_in,
                              void* d_out, int out_size) {
    const float* x     = (const float*)d_in[0];
    const float* w_qkv = (const float*)d_in[1];
    const float* w_out = (const float*)d_in[2];
    float* out = (float*)d_out;

    __half *wqkvh, *wouth, *qkvh, *atth;
    cudaGetSymbolAddress((void**)&wqkvh, g_wqkvh);
    cudaGetSymbolAddress((void**)&wouth, g_wouth);
    cudaGetSymbolAddress((void**)&qkvh, g_qkvh);
    cudaGetSymbolAddress((void**)&atth, g_atth);

    const int qsmem = (2 * ASZ + NSTG * BSZ) * (int)sizeof(__half);  // 55296 B
    const int ksmem = 4 * KSTAGE * (int)sizeof(__half);              // 143360 B
    static bool attr_set = false;
    if (!attr_set) {
        cudaFuncSetAttribute((const void*)hgemm_qkv,
                             cudaFuncAttributeMaxDynamicSharedMemorySize, qsmem);
        cudaFuncSetAttribute((const void*)hgemm_k64<4>,
                             cudaFuncAttributeMaxDynamicSharedMemorySize, ksmem);
        cudaFuncSetAttribute((const void*)natten5,
                             cudaFuncAttributeMaxDynamicSharedMemorySize, (int)NAT5_SMEM);
        attr_set = true;
    }

    // 0) Convert weights only to fp16
    const int NWQ = D_MODEL * QKV_N, NWO = D_MODEL * D_MODEL;
    const int tot4 = (NWQ + NWO) / 4;
    cvt2<<<(tot4 + 255) / 256, 256>>>(w_qkv, wqkvh, NWQ, w_out, wouth, NWO);

    // 1) QKV projection: fused f32-A conversion, plane-scatter epilogue
    hgemm_qkv<<<dim3(QKV_N / 128, M_TOTAL / 128), 256, qsmem>>>(
        x, wqkvh, qkvh, M_TOTAL, QKV_N, D_MODEL);

    // 2) Dense masked neighborhood attention on tensor cores
    natten5<<<dim3(HW / 8, HW / 8, 2 * N_HEADS), 256, NAT5_SMEM>>>(qkvh, atth);

    // 3) Output projection (K-chunk-64 fragment-pipelined)
    hgemm_k64<4><<<dim3(D_MODEL / 128, M_TOTAL / 128), 256, ksmem>>>(
        atth, wouth, out, M_TOTAL, D_MODEL, D_MODEL);
}